// round 5
// baseline (speedup 1.0000x reference)
#include <cuda_runtime.h>
#include <cuda_fp16.h>
#include <cstdint>

#define PADK 136           // halfs per smem row (128 + 8 pad) -> conflict-free LDSM
#define CPAD 132           // floats per C-stage row (128 + 4 pad)
#define FULLMASK 0xffffffffu

// Scratch: per-node transformed features, fp16.
__device__ __half g_Y[(size_t)50000 * 256];
__device__ int g_idx64;

// ---------------------------------------------------------------------------
__device__ __forceinline__ unsigned sptr(const void* p) {
    return (unsigned)__cvta_generic_to_shared(p);
}
__device__ __forceinline__ void ldsm4(unsigned a, unsigned& r0, unsigned& r1,
                                      unsigned& r2, unsigned& r3) {
    asm volatile("ldmatrix.sync.aligned.m8n8.x4.shared.b16 {%0,%1,%2,%3}, [%4];\n"
                 : "=r"(r0), "=r"(r1), "=r"(r2), "=r"(r3) : "r"(a));
}
__device__ __forceinline__ void mma16816(float* c, unsigned a0, unsigned a1,
                                         unsigned a2, unsigned a3,
                                         unsigned b0, unsigned b1) {
    asm volatile(
        "mma.sync.aligned.m16n8k16.row.col.f32.f16.f16.f32 "
        "{%0,%1,%2,%3}, {%4,%5,%6,%7}, {%8,%9}, {%0,%1,%2,%3};\n"
        : "+f"(c[0]), "+f"(c[1]), "+f"(c[2]), "+f"(c[3])
        : "r"(a0), "r"(a1), "r"(a2), "r"(a3), "r"(b0), "r"(b1));
}

// ---------------------------------------------------------------------------
// Node kernel (persistent, block 512, 1 CTA/SM) — unchanged from R4.
// ---------------------------------------------------------------------------
__device__ __forceinline__ void warp_mma_32x64(const __half* Aw, const __half* Bw,
                                               float acc[2][8][4], int lane) {
    unsigned a_addr = sptr(Aw + (size_t)(lane & 15) * PADK + ((lane & 16) ? 8 : 0));
    unsigned b_addr = sptr(Bw + (size_t)((lane & 7) + ((lane & 16) ? 8 : 0)) * PADK
                              + ((lane & 8) ? 8 : 0));
    #pragma unroll
    for (int k0 = 0; k0 < 128; k0 += 16) {
        unsigned a0[4], a1[4];
        ldsm4(a_addr + k0 * 2, a0[0], a0[1], a0[2], a0[3]);
        ldsm4(a_addr + 16 * PADK * 2 + k0 * 2, a1[0], a1[1], a1[2], a1[3]);
        #pragma unroll
        for (int np = 0; np < 4; np++) {
            unsigned b0, b1, b2, b3;
            ldsm4(b_addr + (unsigned)(np * 16 * PADK * 2) + k0 * 2, b0, b1, b2, b3);
            mma16816(acc[0][2 * np],     a0[0], a0[1], a0[2], a0[3], b0, b1);
            mma16816(acc[0][2 * np + 1], a0[0], a0[1], a0[2], a0[3], b2, b3);
            mma16816(acc[1][2 * np],     a1[0], a1[1], a1[2], a1[3], b0, b1);
            mma16816(acc[1][2 * np + 1], a1[0], a1[1], a1[2], a1[3], b2, b3);
        }
    }
}

__global__ __launch_bounds__(512, 1)
void node_gemm_kernel(const float* __restrict__ x,
                      const float* __restrict__ W1,
                      const void* __restrict__ ei,
                      int n_nodes) {
    extern __shared__ __half smem[];
    __half* As0 = smem;
    __half* As1 = smem + 128 * PADK;
    __half* Ws  = smem + 2 * 128 * PADK;   // [256 out-cols][PADK k]

    const int tid = threadIdx.x;

    if (blockIdx.x == 0 && tid < 32) {
        const unsigned* w = (const unsigned*)ei;
        unsigned v = w[2 * tid + 1] | w[2 * (tid + 32) + 1];
        int any_nz = __any_sync(FULLMASK, v != 0u);
        if (tid == 0) g_idx64 = any_nz ? 0 : 1;
    }

    for (int i = tid; i < 256 * 128; i += 512) {
        int c = i & 255, k = i >> 8;
        Ws[(size_t)c * PADK + k] =
            __float2half(W1[(size_t)(k + ((c >> 7) << 7)) * 128 + (c & 127)]);
    }

    const int warp = tid >> 5, lane = tid & 31;
    const int wm = warp & 3, wn = warp >> 2;   // 4M x 4N
    const int g = lane >> 2, t = lane & 3;
    const int n_tiles = (n_nodes + 127) >> 7;

    int li = 0;
    for (int tile = blockIdx.x; tile < n_tiles; tile += gridDim.x, li++) {
        __half* As = (li & 1) ? As1 : As0;
        const int row0 = tile << 7;

        for (int i = tid; i < 128 * 32; i += 512) {
            int r = i >> 5, c4 = i & 31;
            int gr = row0 + r;
            float4 v = make_float4(0.f, 0.f, 0.f, 0.f);
            if (gr < n_nodes) v = ((const float4*)x)[(size_t)gr * 32 + c4];
            __half* dst = As + (size_t)r * PADK + c4 * 4;
            dst[0] = __float2half(v.x); dst[1] = __float2half(v.y);
            dst[2] = __float2half(v.z); dst[3] = __float2half(v.w);
        }
        __syncthreads();

        float acc[2][8][4];
        #pragma unroll
        for (int mi = 0; mi < 2; mi++)
            #pragma unroll
            for (int n8 = 0; n8 < 8; n8++)
                acc[mi][n8][0] = acc[mi][n8][1] = acc[mi][n8][2] = acc[mi][n8][3] = 0.f;

        warp_mma_32x64(As + (size_t)(wm * 32) * PADK,
                       Ws + (size_t)(wn * 64) * PADK, acc, lane);

        #pragma unroll
        for (int mi = 0; mi < 2; mi++) {
            const int r0 = row0 + wm * 32 + mi * 16 + g;
            #pragma unroll
            for (int n8 = 0; n8 < 8; n8++) {
                int col = wn * 64 + n8 * 8 + 2 * t;
                if (r0 < n_nodes)
                    *(__half2*)(g_Y + (size_t)r0 * 256 + col) =
                        __floats2half2_rn(acc[mi][n8][0], acc[mi][n8][1]);
                if (r0 + 8 < n_nodes)
                    *(__half2*)(g_Y + (size_t)(r0 + 8) * 256 + col) =
                        __floats2half2_rn(acc[mi][n8][2], acc[mi][n8][3]);
            }
        }
    }
}

// ---------------------------------------------------------------------------
// Edge kernel (persistent, block 256, 1 CTA/SM):
//   h = relu(Y[src,:128] + Y[dst,128:] + b1);  out = h @ W2 + b2
// W2 fragments preloaded into registers (no per-tile B LDSM).
// Epilogue staged through smem for fully coalesced STG.128.
// Warps: 4M x 2N (32x64 tiles).
// ---------------------------------------------------------------------------
__global__ __launch_bounds__(256, 1)
void edge_kernel(const void* __restrict__ edge_index,
                 const float* __restrict__ b1,
                 const float* __restrict__ W2,
                 const float* __restrict__ b2,
                 float* __restrict__ out,
                 int n_edges) {
    extern __shared__ char dsm[];
    __half* Hs0 = (__half*)dsm;                       // [128][PADK]
    __half* Hs1 = (__half*)(dsm + 34816);
    float*  Cs  = (float*)(dsm + 69632);              // [128][CPAD] fp32 stage
    __half* Ws  = (__half*)(dsm + 69632);             // overlay (preload only)

    const int tid = threadIdx.x;
    const int warp = tid >> 5, lane = tid & 31;
    const int wm = warp & 3, wn = warp >> 2;          // 4M x 2N
    const int g = lane >> 2, t = lane & 3;

    // ---- stage W2 (transposed) then preload fragments into registers ----
    for (int i = tid; i < 128 * 128; i += 256) {
        int k = i >> 7, n = i & 127;
        Ws[(size_t)n * PADK + k] = __float2half(W2[i]);   // W2[k*128+n]
    }
    __syncthreads();

    unsigned Breg[8][4][4];   // [k-step][n-pair][frag]
    {
        unsigned b_addr = sptr(Ws + (size_t)(wn * 64 + (lane & 7) +
                               ((lane & 16) ? 8 : 0)) * PADK + ((lane & 8) ? 8 : 0));
        #pragma unroll
        for (int ks = 0; ks < 8; ks++)
            #pragma unroll
            for (int np = 0; np < 4; np++)
                ldsm4(b_addr + (unsigned)(np * 16 * PADK * 2) + ks * 32,
                      Breg[ks][np][0], Breg[ks][np][1],
                      Breg[ks][np][2], Breg[ks][np][3]);
    }
    __syncthreads();   // Ws region now free for Cs reuse

    // per-lane constants
    const float4 b1v = *(const float4*)(b1 + lane * 4);
    // epilogue output mapping: row = tid>>3 (+32*rr), col = (tid&7)*4 (+32*cc)
    float4 b2v[4];
    #pragma unroll
    for (int cc = 0; cc < 4; cc++)
        b2v[cc] = *(const float4*)(b2 + (tid & 7) * 4 + cc * 32);

    const int is64 = g_idx64;
    const long long* idx64 = (const long long*)edge_index;
    const int*       idx32 = (const int*)edge_index;
    const int n_tiles = (n_edges + 127) >> 7;

    int li = 0;
    for (int tile = blockIdx.x; tile < n_tiles; tile += gridDim.x, li++) {
        __half* Hs = (li & 1) ? Hs1 : Hs0;
        const int e0 = tile << 7;

        // ---- warp-cooperative gather (batched x4 for MLP) ----
        {
            int myE = e0 + (warp << 4) + (lane & 15);
            if (myE >= n_edges) myE = n_edges - 1;
            size_t off = (lane < 16) ? (size_t)myE : (size_t)n_edges + (size_t)myE;
            int vidx = is64 ? (int)idx64[off] : idx32[off];

            __half* Hrow = Hs + (size_t)(warp << 4) * PADK + lane * 4;
            #pragma unroll
            for (int i = 0; i < 16; i += 4) {
                uint2 va[4], vd[4];
                #pragma unroll
                for (int j = 0; j < 4; j++) {
                    int s = __shfl_sync(FULLMASK, vidx, i + j);
                    int d = __shfl_sync(FULLMASK, vidx, 16 + i + j);
                    va[j] = *(const uint2*)(g_Y + (size_t)s * 256 + lane * 4);
                    vd[j] = *(const uint2*)(g_Y + (size_t)d * 256 + 128 + lane * 4);
                }
                #pragma unroll
                for (int j = 0; j < 4; j++) {
                    float2 fa0 = __half22float2(*(const __half2*)&va[j].x);
                    float2 fd0 = __half22float2(*(const __half2*)&vd[j].x);
                    float2 fa1 = __half22float2(*(const __half2*)&va[j].y);
                    float2 fd1 = __half22float2(*(const __half2*)&vd[j].y);
                    __half2 r0 = __floats2half2_rn(fmaxf(fa0.x + fd0.x + b1v.x, 0.f),
                                                   fmaxf(fa0.y + fd0.y + b1v.y, 0.f));
                    __half2 r1 = __floats2half2_rn(fmaxf(fa1.x + fd1.x + b1v.z, 0.f),
                                                   fmaxf(fa1.y + fd1.y + b1v.w, 0.f));
                    uint2 rv;
                    rv.x = *(const unsigned*)&r0;
                    rv.y = *(const unsigned*)&r1;
                    *(uint2*)(Hrow + (size_t)(i + j) * PADK) = rv;
                }
            }
        }
        __syncthreads();   // H ready; also Cs of previous tile fully drained

        // ---- 32x64 warp-tile GEMM: A from smem (LDSM), B from registers ----
        float acc[2][8][4];
        #pragma unroll
        for (int mi = 0; mi < 2; mi++)
            #pragma unroll
            for (int n8 = 0; n8 < 8; n8++)
                acc[mi][n8][0] = acc[mi][n8][1] = acc[mi][n8][2] = acc[mi][n8][3] = 0.f;

        {
            unsigned a_addr = sptr(Hs + (size_t)(wm * 32 + (lane & 15)) * PADK +
                                   ((lane & 16) ? 8 : 0));
            #pragma unroll
            for (int ks = 0; ks < 8; ks++) {
                unsigned a0[4], a1[4];
                ldsm4(a_addr + ks * 32, a0[0], a0[1], a0[2], a0[3]);
                ldsm4(a_addr + 16 * PADK * 2 + ks * 32, a1[0], a1[1], a1[2], a1[3]);
                #pragma unroll
                for (int np = 0; np < 4; np++) {
                    mma16816(acc[0][2 * np],     a0[0], a0[1], a0[2], a0[3],
                             Breg[ks][np][0], Breg[ks][np][1]);
                    mma16816(acc[0][2 * np + 1], a0[0], a0[1], a0[2], a0[3],
                             Breg[ks][np][2], Breg[ks][np][3]);
                    mma16816(acc[1][2 * np],     a1[0], a1[1], a1[2], a1[3],
                             Breg[ks][np][0], Breg[ks][np][1]);
                    mma16816(acc[1][2 * np + 1], a1[0], a1[1], a1[2], a1[3],
                             Breg[ks][np][2], Breg[ks][np][3]);
                }
            }
        }

        // ---- stage C to smem (fp32) ----
        #pragma unroll
        for (int mi = 0; mi < 2; mi++) {
            const int r = wm * 32 + mi * 16 + g;
            #pragma unroll
            for (int n8 = 0; n8 < 8; n8++) {
                int col = wn * 64 + n8 * 8 + 2 * t;
                *(float2*)(Cs + (size_t)r * CPAD + col) =
                    make_float2(acc[mi][n8][0], acc[mi][n8][1]);
                *(float2*)(Cs + (size_t)(r + 8) * CPAD + col) =
                    make_float2(acc[mi][n8][2], acc[mi][n8][3]);
            }
        }
        __syncthreads();   // C complete; H[li&1] fully consumed

        // ---- coalesced store: +b2, STG.128 ----
        {
            const int rl = tid >> 3;            // 0..31
            const int cl = (tid & 7) * 4;       // 0..28
            #pragma unroll
            for (int rr = 0; rr < 4; rr++) {
                const int row = e0 + rr * 32 + rl;
                if (row < n_edges) {
                    float* op = out + (size_t)row * 128;
                    const float* cp = Cs + (size_t)(rr * 32 + rl) * CPAD;
                    #pragma unroll
                    for (int cc = 0; cc < 4; cc++) {
                        float4 v = *(const float4*)(cp + cl + cc * 32);
                        v.x += b2v[cc].x; v.y += b2v[cc].y;
                        v.z += b2v[cc].z; v.w += b2v[cc].w;
                        *(float4*)(op + cl + cc * 32) = v;
                    }
                }
            }
        }
        // next iteration's first __syncthreads orders Cs reuse
    }
}

// ---------------------------------------------------------------------------
extern "C" void kernel_launch(void* const* d_in, const int* in_sizes, int n_in,
                              void* d_out, int out_size) {
    const float* x  = (const float*)d_in[0];
    const void*  ei = d_in[1];
    const float* W1 = (const float*)d_in[2];
    const float* b1 = (const float*)d_in[3];
    const float* W2 = (const float*)d_in[4];
    const float* b2 = (const float*)d_in[5];
    float* out = (float*)d_out;

    const int n_nodes = in_sizes[0] / 128;
    const int n_edges = in_sizes[1] / 2;

    const int node_smem = (2 * 128 + 256) * PADK * (int)sizeof(__half);    // 139264
    const int edge_smem = 69632 + 128 * CPAD * (int)sizeof(float);          // 137216
    static bool attr_set = false;
    if (!attr_set) {
        cudaFuncSetAttribute(node_gemm_kernel,
                             cudaFuncAttributeMaxDynamicSharedMemorySize, node_smem);
        cudaFuncSetAttribute(edge_kernel,
                             cudaFuncAttributeMaxDynamicSharedMemorySize, edge_smem);
        attr_set = true;
    }

    const int node_tiles = (n_nodes + 127) / 128;
    int g1 = node_tiles < 152 ? node_tiles : 152;
    node_gemm_kernel<<<g1, 512, node_smem>>>(x, W1, ei, n_nodes);

    const int edge_tiles = (n_edges + 127) / 128;
    int g2 = edge_tiles < 152 ? edge_tiles : 152;
    edge_kernel<<<g2, 256, edge_smem>>>(ei, b1, W2, b2, out, n_edges);
}